// round 16
// baseline (speedup 1.0000x reference)
#include <cuda_runtime.h>
#include <cuda_bf16.h>
#include <cstdint>

#define NROW 8192
#define NEXT 8320   // NROW + 128 dummy rows

__device__ float4 g_zn[NROW * 32];
__device__ uint4  g_zbf[NROW * 16];   // normalized bf16 rows, 256B each
__device__ float2 g_meta[NROW];       // (sq, bits: L | S<<8)
__device__ uint4  g_zl[NEXT * 16];    // label-sorted bf16 rows (dummy tail stays zero)
__device__ uint4  g_zs[NEXT * 16];    // subject-sorted bf16 rows
__device__ float2 g_ml[NEXT];         // (sq,  orig | subj<<13)  pos side
__device__ float2 g_ms[NEXT];         // (-sq, orig | label<<13) neg side
__device__ unsigned g_hist[48], g_start[48], g_cur[48];
__device__ unsigned long long g_pos[NROW];
__device__ unsigned long long g_neg[NROW];
__device__ unsigned long long g_acc;
__device__ unsigned g_done;

static __device__ __forceinline__ unsigned ford(float f) {
    unsigned u = __float_as_uint(f);
    return (u & 0x80000000u) ? ~u : (u | 0x80000000u);
}
static __device__ __forceinline__ uint32_t smem_u32(const void* p) {
    uint32_t a;
    asm("{ .reg .u64 t; cvta.to.shared.u64 t, %1; cvt.u32.u64 %0, t; }" : "=r"(a) : "l"(p));
    return a;
}
static __device__ __forceinline__ void cpa16(uint32_t dst, const void* src) {
    asm volatile("cp.async.cg.shared.global [%0], [%1], 16;" :: "r"(dst), "l"(src));
}
static __device__ __forceinline__ void cpcommit() {
    asm volatile("cp.async.commit_group;" ::: "memory");
}
template <int N> static __device__ __forceinline__ void cpwaitn() {
    asm volatile("cp.async.wait_group %0;" :: "n"(N) : "memory");
}
static __device__ __forceinline__ void ldm4(uint32_t& r0, uint32_t& r1, uint32_t& r2,
                                            uint32_t& r3, uint32_t addr) {
    asm volatile("ldmatrix.sync.aligned.m8n8.x4.shared.b16 {%0,%1,%2,%3}, [%4];"
                 : "=r"(r0), "=r"(r1), "=r"(r2), "=r"(r3) : "r"(addr));
}
static __device__ __forceinline__ void mma16816(float* c, const uint32_t* a,
                                                uint32_t b0, uint32_t b1) {
    asm volatile(
        "mma.sync.aligned.m16n8k16.row.col.f32.bf16.bf16.f32 "
        "{%0,%1,%2,%3}, {%4,%5,%6,%7}, {%8,%9}, {%0,%1,%2,%3};"
        : "+f"(c[0]), "+f"(c[1]), "+f"(c[2]), "+f"(c[3])
        : "r"(a[0]), "r"(a[1]), "r"(a[2]), "r"(a[3]), "r"(b0), "r"(b1));
}
static __device__ __forceinline__ uint32_t sw_off(int row, int chunk) {
    return (uint32_t)(row * 256 + ((chunk ^ (row & 7)) << 4));
}
static __device__ __forceinline__ void upd2(float key, bool elig, int j,
                                            float& bk, int& bj) {
    bool u = elig & (key > bk);
    bk = u ? key : bk;
    bj = u ? j : bj;
}

// ---- init: zero counters + write dummy sentinel metas (tiny) ----
__global__ void k_init() {
    int t = threadIdx.x;
    if (t < 48) { g_hist[t] = 0u; g_cur[t] = 0u; }
    if (t < 128) {
        g_ml[8192 + t] = make_float2(-1e30f, __uint_as_float(0x1FFFu));
        g_ms[8192 + t] = make_float2(-1e30f, __uint_as_float(0x1FFFu));
    }
}

// ---- prep: normalize, copies, meta, sentinels, histogram ----
__global__ void k_prep(const float* __restrict__ z, const int* __restrict__ lab,
                       const int* __restrict__ sub) {
    int row = blockIdx.x * 8 + (threadIdx.x >> 5);
    int lane = threadIdx.x & 31;
    float4 v = reinterpret_cast<const float4*>(z)[row * 32 + lane];
    float ss = v.x * v.x + v.y * v.y + v.z * v.z + v.w * v.w;
#pragma unroll
    for (int o = 16; o; o >>= 1) ss += __shfl_xor_sync(0xFFFFFFFFu, ss, o);
    float inv = 1.0f / fmaxf(sqrtf(ss), 1e-12f);
    float4 zn = make_float4(v.x * inv, v.y * inv, v.z * inv, v.w * inv);
    g_zn[row * 32 + lane] = zn;
    unsigned s0 = __bfloat16_as_ushort(__float2bfloat16_rn(zn.x));
    unsigned s1 = __bfloat16_as_ushort(__float2bfloat16_rn(zn.y));
    unsigned s2 = __bfloat16_as_ushort(__float2bfloat16_rn(zn.z));
    unsigned s3 = __bfloat16_as_ushort(__float2bfloat16_rn(zn.w));
    uint2 pkv;
    pkv.x = s0 | (s1 << 16);
    pkv.y = s2 | (s3 << 16);
    reinterpret_cast<uint2*>(g_zbf)[row * 32 + lane] = pkv;
    float sq = zn.x * zn.x + zn.y * zn.y + zn.z * zn.z + zn.w * zn.w;
#pragma unroll
    for (int o = 16; o; o >>= 1) sq += __shfl_xor_sync(0xFFFFFFFFu, sq, o);
    if (lane == 0) {
        unsigned L = (unsigned)lab[row] & 15u, S = (unsigned)sub[row] & 31u;
        g_meta[row] = make_float2(sq, __uint_as_float(L | (S << 8)));
        g_pos[row] = 0ull;
        g_neg[row] = 0xFFFFFFFFFFFFFFFFull;
        atomicAdd(&g_hist[L], 1u);
        atomicAdd(&g_hist[16 + S], 1u);
        if (row == 0) { g_acc = 0ull; g_done = 0u; }
    }
}

// ---- scatter: local scan of g_hist, write g_start, scatter rows ----
__global__ void k_scatter() {
    __shared__ unsigned hcnt[48], hbase[48], sstart[48], sp1[256], sp2[256];
    int t = threadIdx.x;
    int row = blockIdx.x * 256 + t;
    if (t < 48) hcnt[t] = 0;
    if (t == 0) {
        unsigned s = 0;
        for (int i = 0; i < 16; i++) { sstart[i] = s; s += g_hist[i]; }
    } else if (t == 32) {
        unsigned s = 0;
        for (int i = 0; i < 32; i++) { sstart[16 + i] = s; s += g_hist[16 + i]; }
    }
    __syncthreads();
    if (t < 48) g_start[t] = sstart[t];   // all blocks write identical values
    float2 m = g_meta[row];
    unsigned c = __float_as_uint(m.y);
    unsigned L = c & 15u, S = (c >> 8) & 31u;
    unsigned r1 = atomicAdd(&hcnt[L], 1u);
    unsigned r2 = atomicAdd(&hcnt[16 + S], 1u);
    __syncthreads();
    if (t < 48 && hcnt[t]) hbase[t] = sstart[t] + atomicAdd(&g_cur[t], hcnt[t]);
    __syncthreads();
    unsigned p1 = hbase[L] + r1, p2 = hbase[16 + S] + r2;
    sp1[t] = p1; sp2[t] = p2;
    g_ml[p1] = make_float2(m.x,  __uint_as_float((unsigned)row | (S << 13)));
    g_ms[p2] = make_float2(-m.x, __uint_as_float((unsigned)row | (L << 13)));
    __syncthreads();
    int rb = blockIdx.x * 256;
    for (int idx = t; idx < 4096; idx += 256) {
        int r = idx >> 4, qq = idx & 15;
        uint4 v = g_zbf[(size_t)(rb + r) * 16 + qq];
        g_zl[(size_t)sp1[r] * 16 + qq] = v;
        g_zs[(size_t)sp2[r] * 16 + qq] = v;
    }
}

// ---- mine: one 128(i) x 64(j) tile per CTA ----
#define SM_A 0
#define SM_B 32768
#define SM_M 49152
#define SM_TOT 49664

__global__ void __launch_bounds__(256, 2) k_mine() {
    const int bid = blockIdx.x;
    bool posm; unsigned sg, ng; int ti, tj;
    const uint4* Z; const float2* M;
    if (bid < 2048) {
        posm = true;
        int g = bid >> 7, pr = bid & 127;
        ti = pr >> 4; tj = pr & 15;
        ng = g_hist[g]; sg = g_start[g];
        Z = g_zl; M = g_ml;
    } else {
        posm = false;
        int b = bid - 2048;
        int g = b >> 5, pr = b & 31;
        ti = pr >> 3; tj = pr & 7;
        ng = g_hist[16 + g]; sg = g_start[16 + g];
        Z = g_zs; M = g_ms;
    }
    if ((unsigned)(ti * 128) >= ng || (unsigned)(tj * 64) >= ng) return;

    extern __shared__ char dynsm[];
    const int tid = threadIdx.x, w = tid >> 5, lane = tid & 31;
    const uint32_t sb = smem_u32(dynsm);

    for (int idx = tid; idx < 2048; idx += 256) {
        int r = idx >> 4, qq = idx & 15;
        int ra = ti * 128 + r;
        unsigned ga = ((unsigned)ra < ng) ? sg + ra : 8192u + r;
        cpa16(sb + SM_A + sw_off(r, qq), &Z[(size_t)ga * 16 + qq]);
        if (idx < 1024) {
            int rbx = tj * 64 + r;
            unsigned gb = ((unsigned)rbx < ng) ? sg + rbx : 8192u + r;
            cpa16(sb + SM_B + sw_off(r, qq), &Z[(size_t)gb * 16 + qq]);
        }
    }
    float2* smM = reinterpret_cast<float2*>(dynsm + SM_M);
    if (tid < 64) {
        int rj = tj * 64 + tid;
        unsigned gb = ((unsigned)rj < ng) ? sg + rj : 8192u + tid;
        smM[tid] = M[gb];   // plain 8B load/store: float2 is only 8B-aligned
    }
    cpcommit();
    cpwaitn<0>();
    __syncthreads();

    uint32_t A[8][4];
    {
        int r = w * 16 + ((lane >> 3) & 1) * 8 + (lane & 7);
        int cb = lane >> 4;
#pragma unroll
        for (int s = 0; s < 8; s++)
            ldm4(A[s][0], A[s][1], A[s][2], A[s][3], sb + SM_A + sw_off(r, 2 * s + cb));
    }

    const int rl0 = ti * 128 + w * 16 + (lane >> 2);
    const int rl1 = rl0 + 8;
    const bool v0 = (unsigned)rl0 < ng, v1 = (unsigned)rl1 < ng;
    const unsigned ga0 = v0 ? sg + rl0 : 8192u;
    const unsigned ga1 = v1 ? sg + rl1 : 8192u;
    const unsigned b0a = __float_as_uint(__ldg(&M[ga0].y));
    const unsigned b1a = __float_as_uint(__ldg(&M[ga1].y));
    const unsigned mc0 = b0a >> 13, mc1 = b1a >> 13;
    const unsigned oa0 = b0a & 0x1FFFu, oa1 = b1a & 0x1FFFu;
    const float coef = posm ? -2.f : 2.f;

    float bk0[2] = {-1e30f, -1e30f}, bk1[2] = {-1e30f, -1e30f};
    int bj0[2] = {-1, -1}, bj1[2] = {-1, -1};
    const int q = lane & 3;
    const int cadd = (lane >> 3) & 1;
    const int nbase = ((lane >> 4) << 3) + (lane & 7);

#pragma unroll
    for (int np = 0; np < 4; np++) {
        const int n = np * 16 + nbase;
        float a0[4] = {0.f, 0.f, 0.f, 0.f}, a1[4] = {0.f, 0.f, 0.f, 0.f};
#pragma unroll
        for (int s = 0; s < 8; s++) {
            uint32_t t0, t1, t2, t3;
            ldm4(t0, t1, t2, t3, sb + SM_B + sw_off(n, 2 * s + cadd));
            mma16816(a0, A[s], t0, t1);
            mma16816(a1, A[s], t2, t3);
        }
#pragma unroll
        for (int h = 0; h < 2; h++) {
            const int nt = 2 * np + h;
            const float* av = h ? a1 : a0;
            float4 mm = *reinterpret_cast<const float4*>(&smM[nt * 8 + q * 2]);
            unsigned jb0 = __float_as_uint(mm.y), jb1 = __float_as_uint(mm.w);
            unsigned cj0 = jb0 >> 13, cj1 = jb1 >> 13;
            int j0 = (int)(jb0 & 0x1FFFu), j1 = (int)(jb1 & 0x1FFFu);
            upd2(fmaf(coef, av[0], mm.x), cj0 != mc0, j0, bk0[h], bj0[h]);
            upd2(fmaf(coef, av[1], mm.z), cj1 != mc0, j1, bk0[h], bj0[h]);
            upd2(fmaf(coef, av[2], mm.x), cj0 != mc1, j0, bk1[h], bj1[h]);
            upd2(fmaf(coef, av[3], mm.z), cj1 != mc1, j1, bk1[h], bj1[h]);
        }
    }

    unsigned long long V0 = 0ull, V1 = 0ull;
#pragma unroll
    for (int s = 0; s < 2; s++) {
        if (bj0[s] >= 0) {
            unsigned long long cd = ((unsigned long long)ford(bk0[s]) << 32) |
                                    (unsigned)(0xFFFFFFFFu - (unsigned)bj0[s]);
            if (cd > V0) V0 = cd;
        }
        if (bj1[s] >= 0) {
            unsigned long long cd = ((unsigned long long)ford(bk1[s]) << 32) |
                                    (unsigned)(0xFFFFFFFFu - (unsigned)bj1[s]);
            if (cd > V1) V1 = cd;
        }
    }
#pragma unroll
    for (int o = 1; o <= 2; o <<= 1) {
        unsigned long long x;
        x = __shfl_xor_sync(0xFFFFFFFFu, V0, o); if (x > V0) V0 = x;
        x = __shfl_xor_sync(0xFFFFFFFFu, V1, o); if (x > V1) V1 = x;
    }
    if ((lane & 3) == 0) {
        if (posm) {
            if (V0 && v0) atomicMax(&g_pos[oa0], V0);
            if (V1 && v1) atomicMax(&g_pos[oa1], V1);
        } else {
            // tracked max of -key; ford(-x) == ~ford(x); low word becomes plain j
            if (V0 && v0) {
                unsigned long long nv = ((unsigned long long)(~(unsigned)(V0 >> 32)) << 32) |
                                        (0xFFFFFFFFu - (unsigned)(V0 & 0xFFFFFFFFull));
                atomicMin(&g_neg[oa0], nv);
            }
            if (V1 && v1) {
                unsigned long long nv = ((unsigned long long)(~(unsigned)(V1 >> 32)) << 32) |
                                        (0xFFFFFFFFu - (unsigned)(V1 & 0xFFFFFFFFull));
                atomicMin(&g_neg[oa1], nv);
            }
        }
    }
}

// ---- pair: exact fp32 recompute + deterministic fixed-point reduce ----
__global__ void k_pair(float* __restrict__ out) {
    __shared__ float sper[8];
    __shared__ int scnt[8];
    int w = threadIdx.x >> 5, lane = threadIdx.x & 31;
    int i = blockIdx.x * 8 + w;
    unsigned long long bp = g_pos[i], bn = g_neg[i];
    bool valid = (bp != 0ull) && (bn != 0xFFFFFFFFFFFFFFFFull);
    int pj = (int)(0xFFFFFFFFu - (unsigned)(bp & 0xFFFFFFFFull));
    int nj = (int)(unsigned)(bn & 0xFFFFFFFFull);   // neg side stores plain j
    if (!valid) { pj = 0; nj = 0; }
    float4 a = g_zn[i * 32 + lane];
    float4 p = g_zn[pj * 32 + lane];
    float4 n = g_zn[nj * 32 + lane];
    const float e = 1e-6f;
    float dx, s1 = 0.f, s2 = 0.f;
    dx = a.x - p.x + e; s1 += dx * dx;
    dx = a.y - p.y + e; s1 += dx * dx;
    dx = a.z - p.z + e; s1 += dx * dx;
    dx = a.w - p.w + e; s1 += dx * dx;
    dx = a.x - n.x + e; s2 += dx * dx;
    dx = a.y - n.y + e; s2 += dx * dx;
    dx = a.z - n.z + e; s2 += dx * dx;
    dx = a.w - n.w + e; s2 += dx * dx;
#pragma unroll
    for (int o = 16; o; o >>= 1) {
        s1 += __shfl_xor_sync(0xFFFFFFFFu, s1, o);
        s2 += __shfl_xor_sync(0xFFFFFFFFu, s2, o);
    }
    if (lane == 0) {
        float per = fmaxf(sqrtf(s1) - sqrtf(s2) + 0.2f, 0.f);
        sper[w] = valid ? per : 0.f;
        scnt[w] = valid ? 1 : 0;
    }
    __syncthreads();
    if (threadIdx.x == 0) {
        float bs = 0.f;
        int bc = 0;
#pragma unroll
        for (int k = 0; k < 8; k++) { bs += sper[k]; bc += scnt[k]; }
        unsigned long long fx = (unsigned long long)(bs * 16777216.0f + 0.5f);
        atomicAdd(&g_acc, (fx << 14) | (unsigned long long)bc);
        __threadfence();
        unsigned old = atomicAdd(&g_done, 1u);
        if (old == gridDim.x - 1) {
            unsigned long long acc = atomicAdd(&g_acc, 0ull);
            unsigned cnt = (unsigned)(acc & 0x3FFFull);
            float sum = (float)(acc >> 14) * (1.0f / 16777216.0f);
            out[0] = cnt ? sum / (float)cnt : 0.f;
        }
    }
}

extern "C" void kernel_launch(void* const* d_in, const int* in_sizes, int n_in,
                              void* d_out, int out_size) {
    const float* z = (const float*)d_in[0];
    const int* lab = (const int*)d_in[1];
    const int* sub = (const int*)d_in[2];
    cudaFuncSetAttribute(k_mine, cudaFuncAttributeMaxDynamicSharedMemorySize, SM_TOT);
    k_init<<<1, 256>>>();
    k_prep<<<1024, 256>>>(z, lab, sub);
    k_scatter<<<32, 256>>>();
    k_mine<<<3072, 256, SM_TOT>>>();
    k_pair<<<1024, 256>>>((float*)d_out);
}

// round 17
// speedup vs baseline: 1.2459x; 1.2459x over previous
#include <cuda_runtime.h>
#include <cuda_bf16.h>
#include <cstdint>

#define NROW 8192
#define NEXT 8320   // NROW + 128 dummy rows

__device__ float4 g_zn[NROW * 32];
__device__ uint4  g_zbf[NROW * 16];   // normalized bf16 rows, 256B each
__device__ float2 g_meta[NROW];       // (sq, bits: L | S<<8)
__device__ uint4  g_zl[NEXT * 16];    // label-sorted bf16 rows (dummy tail stays zero)
__device__ uint4  g_zs[NEXT * 16];    // subject-sorted bf16 rows
__device__ float2 g_ml[NEXT];         // (sq,  orig | subj<<13)  pos side
__device__ float2 g_ms[NEXT];         // (-sq, orig | label<<13) neg side
__device__ unsigned g_hist[48], g_start[48], g_cur[48];
__device__ unsigned long long g_pos[NROW];
__device__ unsigned long long g_neg[NROW];
__device__ unsigned long long g_acc;
__device__ unsigned g_done;

static __device__ __forceinline__ unsigned ford(float f) {
    unsigned u = __float_as_uint(f);
    return (u & 0x80000000u) ? ~u : (u | 0x80000000u);
}
static __device__ __forceinline__ uint32_t smem_u32(const void* p) {
    uint32_t a;
    asm("{ .reg .u64 t; cvta.to.shared.u64 t, %1; cvt.u32.u64 %0, t; }" : "=r"(a) : "l"(p));
    return a;
}
static __device__ __forceinline__ void cpa16(uint32_t dst, const void* src) {
    asm volatile("cp.async.cg.shared.global [%0], [%1], 16;" :: "r"(dst), "l"(src));
}
static __device__ __forceinline__ void cpcommit() {
    asm volatile("cp.async.commit_group;" ::: "memory");
}
template <int N> static __device__ __forceinline__ void cpwaitn() {
    asm volatile("cp.async.wait_group %0;" :: "n"(N) : "memory");
}
static __device__ __forceinline__ void ldm4(uint32_t& r0, uint32_t& r1, uint32_t& r2,
                                            uint32_t& r3, uint32_t addr) {
    asm volatile("ldmatrix.sync.aligned.m8n8.x4.shared.b16 {%0,%1,%2,%3}, [%4];"
                 : "=r"(r0), "=r"(r1), "=r"(r2), "=r"(r3) : "r"(addr));
}
static __device__ __forceinline__ void mma16816(float* c, const uint32_t* a,
                                                uint32_t b0, uint32_t b1) {
    asm volatile(
        "mma.sync.aligned.m16n8k16.row.col.f32.bf16.bf16.f32 "
        "{%0,%1,%2,%3}, {%4,%5,%6,%7}, {%8,%9}, {%0,%1,%2,%3};"
        : "+f"(c[0]), "+f"(c[1]), "+f"(c[2]), "+f"(c[3])
        : "r"(a[0]), "r"(a[1]), "r"(a[2]), "r"(a[3]), "r"(b0), "r"(b1));
}
static __device__ __forceinline__ uint32_t sw_off(int row, int chunk) {
    return (uint32_t)(row * 256 + ((chunk ^ (row & 7)) << 4));
}
static __device__ __forceinline__ void upd2(float key, bool elig, int j,
                                            float& bk, int& bj) {
    bool u = elig & (key > bk);
    bk = u ? key : bk;
    bj = u ? j : bj;
}

// ---- init: zero counters + write dummy sentinel metas (tiny) ----
__global__ void k_init() {
    int t = threadIdx.x;
    if (t < 48) { g_hist[t] = 0u; g_cur[t] = 0u; }
    if (t < 128) {
        g_ml[8192 + t] = make_float2(-1e30f, __uint_as_float(0x1FFFu));
        g_ms[8192 + t] = make_float2(-1e30f, __uint_as_float(0x1FFFu));
    }
}

// ---- hist: block-aggregated label/subject histogram (48 global atomics/block) ----
__global__ void k_hist(const int* __restrict__ lab, const int* __restrict__ sub) {
    __shared__ unsigned sh[48];
    int t = threadIdx.x;
    if (t < 48) sh[t] = 0;
    __syncthreads();
    int row = blockIdx.x * 256 + t;
    atomicAdd(&sh[lab[row] & 15], 1u);
    atomicAdd(&sh[16 + (sub[row] & 31)], 1u);
    __syncthreads();
    if (t < 48 && sh[t]) atomicAdd(&g_hist[t], sh[t]);
}

// ---- prep: normalize, copies, meta, sentinels ----
__global__ void k_prep(const float* __restrict__ z, const int* __restrict__ lab,
                       const int* __restrict__ sub) {
    int row = blockIdx.x * 8 + (threadIdx.x >> 5);
    int lane = threadIdx.x & 31;
    float4 v = reinterpret_cast<const float4*>(z)[row * 32 + lane];
    float ss = v.x * v.x + v.y * v.y + v.z * v.z + v.w * v.w;
#pragma unroll
    for (int o = 16; o; o >>= 1) ss += __shfl_xor_sync(0xFFFFFFFFu, ss, o);
    float inv = 1.0f / fmaxf(sqrtf(ss), 1e-12f);
    float4 zn = make_float4(v.x * inv, v.y * inv, v.z * inv, v.w * inv);
    g_zn[row * 32 + lane] = zn;
    unsigned s0 = __bfloat16_as_ushort(__float2bfloat16_rn(zn.x));
    unsigned s1 = __bfloat16_as_ushort(__float2bfloat16_rn(zn.y));
    unsigned s2 = __bfloat16_as_ushort(__float2bfloat16_rn(zn.z));
    unsigned s3 = __bfloat16_as_ushort(__float2bfloat16_rn(zn.w));
    uint2 pkv;
    pkv.x = s0 | (s1 << 16);
    pkv.y = s2 | (s3 << 16);
    reinterpret_cast<uint2*>(g_zbf)[row * 32 + lane] = pkv;
    float sq = zn.x * zn.x + zn.y * zn.y + zn.z * zn.z + zn.w * zn.w;
#pragma unroll
    for (int o = 16; o; o >>= 1) sq += __shfl_xor_sync(0xFFFFFFFFu, sq, o);
    if (lane == 0) {
        unsigned L = (unsigned)lab[row] & 15u, S = (unsigned)sub[row] & 31u;
        g_meta[row] = make_float2(sq, __uint_as_float(L | (S << 8)));
        g_pos[row] = 0ull;
        g_neg[row] = 0xFFFFFFFFFFFFFFFFull;
        if (row == 0) { g_acc = 0ull; g_done = 0u; }
    }
}

// ---- scatter: local scan of g_hist, write g_start, scatter rows ----
__global__ void k_scatter() {
    __shared__ unsigned hcnt[48], hbase[48], sstart[48], sp1[256], sp2[256];
    int t = threadIdx.x;
    int row = blockIdx.x * 256 + t;
    if (t < 48) hcnt[t] = 0;
    if (t == 0) {
        unsigned s = 0;
        for (int i = 0; i < 16; i++) { sstart[i] = s; s += g_hist[i]; }
    } else if (t == 32) {
        unsigned s = 0;
        for (int i = 0; i < 32; i++) { sstart[16 + i] = s; s += g_hist[16 + i]; }
    }
    __syncthreads();
    if (t < 48) g_start[t] = sstart[t];   // all blocks write identical values
    float2 m = g_meta[row];
    unsigned c = __float_as_uint(m.y);
    unsigned L = c & 15u, S = (c >> 8) & 31u;
    unsigned r1 = atomicAdd(&hcnt[L], 1u);
    unsigned r2 = atomicAdd(&hcnt[16 + S], 1u);
    __syncthreads();
    if (t < 48 && hcnt[t]) hbase[t] = sstart[t] + atomicAdd(&g_cur[t], hcnt[t]);
    __syncthreads();
    unsigned p1 = hbase[L] + r1, p2 = hbase[16 + S] + r2;
    sp1[t] = p1; sp2[t] = p2;
    g_ml[p1] = make_float2(m.x,  __uint_as_float((unsigned)row | (S << 13)));
    g_ms[p2] = make_float2(-m.x, __uint_as_float((unsigned)row | (L << 13)));
    __syncthreads();
    int rb = blockIdx.x * 256;
    for (int idx = t; idx < 4096; idx += 256) {
        int r = idx >> 4, qq = idx & 15;
        uint4 v = g_zbf[(size_t)(rb + r) * 16 + qq];
        g_zl[(size_t)sp1[r] * 16 + qq] = v;
        g_zs[(size_t)sp2[r] * 16 + qq] = v;
    }
}

// ---- mine: one 128(i) x 64(j) tile per CTA, occupancy 3 ----
#define SM_A 0
#define SM_B 32768
#define SM_M 49152
#define SM_TOT 49664

__global__ void __launch_bounds__(256, 3) k_mine() {
    const int bid = blockIdx.x;
    bool posm; unsigned sg, ng; int ti, tj;
    const uint4* Z; const float2* M;
    if (bid < 2048) {
        posm = true;
        int g = bid >> 7, pr = bid & 127;
        ti = pr >> 4; tj = pr & 15;
        ng = g_hist[g]; sg = g_start[g];
        Z = g_zl; M = g_ml;
    } else {
        posm = false;
        int b = bid - 2048;
        int g = b >> 5, pr = b & 31;
        ti = pr >> 3; tj = pr & 7;
        ng = g_hist[16 + g]; sg = g_start[16 + g];
        Z = g_zs; M = g_ms;
    }
    if ((unsigned)(ti * 128) >= ng || (unsigned)(tj * 64) >= ng) return;

    extern __shared__ char dynsm[];
    const int tid = threadIdx.x, w = tid >> 5, lane = tid & 31;
    const uint32_t sb = smem_u32(dynsm);

    for (int idx = tid; idx < 2048; idx += 256) {
        int r = idx >> 4, qq = idx & 15;
        int ra = ti * 128 + r;
        unsigned ga = ((unsigned)ra < ng) ? sg + ra : 8192u + r;
        cpa16(sb + SM_A + sw_off(r, qq), &Z[(size_t)ga * 16 + qq]);
        if (idx < 1024) {
            int rbx = tj * 64 + r;
            unsigned gb = ((unsigned)rbx < ng) ? sg + rbx : 8192u + r;
            cpa16(sb + SM_B + sw_off(r, qq), &Z[(size_t)gb * 16 + qq]);
        }
    }
    float2* smM = reinterpret_cast<float2*>(dynsm + SM_M);
    if (tid < 64) {
        int rj = tj * 64 + tid;
        unsigned gb = ((unsigned)rj < ng) ? sg + rj : 8192u + tid;
        smM[tid] = M[gb];   // plain 8B load/store: float2 is only 8B-aligned
    }
    cpcommit();
    cpwaitn<0>();
    __syncthreads();

    uint32_t A[8][4];
    {
        int r = w * 16 + ((lane >> 3) & 1) * 8 + (lane & 7);
        int cb = lane >> 4;
#pragma unroll
        for (int s = 0; s < 8; s++)
            ldm4(A[s][0], A[s][1], A[s][2], A[s][3], sb + SM_A + sw_off(r, 2 * s + cb));
    }

    const int rl0 = ti * 128 + w * 16 + (lane >> 2);
    const int rl1 = rl0 + 8;
    const bool v0 = (unsigned)rl0 < ng, v1 = (unsigned)rl1 < ng;
    const unsigned ga0 = v0 ? sg + rl0 : 8192u;
    const unsigned ga1 = v1 ? sg + rl1 : 8192u;
    const unsigned b0a = __float_as_uint(__ldg(&M[ga0].y));
    const unsigned b1a = __float_as_uint(__ldg(&M[ga1].y));
    const unsigned mc0 = b0a >> 13, mc1 = b1a >> 13;
    const unsigned oa0 = b0a & 0x1FFFu, oa1 = b1a & 0x1FFFu;
    const float coef = posm ? -2.f : 2.f;

    float bk0[2] = {-1e30f, -1e30f}, bk1[2] = {-1e30f, -1e30f};
    int bj0[2] = {-1, -1}, bj1[2] = {-1, -1};
    const int q = lane & 3;
    const int cadd = (lane >> 3) & 1;
    const int nbase = ((lane >> 4) << 3) + (lane & 7);

#pragma unroll
    for (int np = 0; np < 4; np++) {
        const int n = np * 16 + nbase;
        float a0[4] = {0.f, 0.f, 0.f, 0.f}, a1[4] = {0.f, 0.f, 0.f, 0.f};
#pragma unroll
        for (int s = 0; s < 8; s++) {
            uint32_t t0, t1, t2, t3;
            ldm4(t0, t1, t2, t3, sb + SM_B + sw_off(n, 2 * s + cadd));
            mma16816(a0, A[s], t0, t1);
            mma16816(a1, A[s], t2, t3);
        }
#pragma unroll
        for (int h = 0; h < 2; h++) {
            const int nt = 2 * np + h;
            const float* av = h ? a1 : a0;
            float4 mm = *reinterpret_cast<const float4*>(&smM[nt * 8 + q * 2]);
            unsigned jb0 = __float_as_uint(mm.y), jb1 = __float_as_uint(mm.w);
            unsigned cj0 = jb0 >> 13, cj1 = jb1 >> 13;
            int j0 = (int)(jb0 & 0x1FFFu), j1 = (int)(jb1 & 0x1FFFu);
            upd2(fmaf(coef, av[0], mm.x), cj0 != mc0, j0, bk0[h], bj0[h]);
            upd2(fmaf(coef, av[1], mm.z), cj1 != mc0, j1, bk0[h], bj0[h]);
            upd2(fmaf(coef, av[2], mm.x), cj0 != mc1, j0, bk1[h], bj1[h]);
            upd2(fmaf(coef, av[3], mm.z), cj1 != mc1, j1, bk1[h], bj1[h]);
        }
    }

    unsigned long long V0 = 0ull, V1 = 0ull;
#pragma unroll
    for (int s = 0; s < 2; s++) {
        if (bj0[s] >= 0) {
            unsigned long long cd = ((unsigned long long)ford(bk0[s]) << 32) |
                                    (unsigned)(0xFFFFFFFFu - (unsigned)bj0[s]);
            if (cd > V0) V0 = cd;
        }
        if (bj1[s] >= 0) {
            unsigned long long cd = ((unsigned long long)ford(bk1[s]) << 32) |
                                    (unsigned)(0xFFFFFFFFu - (unsigned)bj1[s]);
            if (cd > V1) V1 = cd;
        }
    }
#pragma unroll
    for (int o = 1; o <= 2; o <<= 1) {
        unsigned long long x;
        x = __shfl_xor_sync(0xFFFFFFFFu, V0, o); if (x > V0) V0 = x;
        x = __shfl_xor_sync(0xFFFFFFFFu, V1, o); if (x > V1) V1 = x;
    }
    if ((lane & 3) == 0) {
        if (posm) {
            if (V0 && v0) atomicMax(&g_pos[oa0], V0);
            if (V1 && v1) atomicMax(&g_pos[oa1], V1);
        } else {
            // tracked max of -key; ford(-x) == ~ford(x); low word becomes plain j
            if (V0 && v0) {
                unsigned long long nv = ((unsigned long long)(~(unsigned)(V0 >> 32)) << 32) |
                                        (0xFFFFFFFFu - (unsigned)(V0 & 0xFFFFFFFFull));
                atomicMin(&g_neg[oa0], nv);
            }
            if (V1 && v1) {
                unsigned long long nv = ((unsigned long long)(~(unsigned)(V1 >> 32)) << 32) |
                                        (0xFFFFFFFFu - (unsigned)(V1 & 0xFFFFFFFFull));
                atomicMin(&g_neg[oa1], nv);
            }
        }
    }
}

// ---- pair: exact fp32 recompute + deterministic fixed-point reduce ----
__global__ void k_pair(float* __restrict__ out) {
    __shared__ float sper[8];
    __shared__ int scnt[8];
    int w = threadIdx.x >> 5, lane = threadIdx.x & 31;
    int i = blockIdx.x * 8 + w;
    unsigned long long bp = g_pos[i], bn = g_neg[i];
    bool valid = (bp != 0ull) && (bn != 0xFFFFFFFFFFFFFFFFull);
    int pj = (int)(0xFFFFFFFFu - (unsigned)(bp & 0xFFFFFFFFull));
    int nj = (int)(unsigned)(bn & 0xFFFFFFFFull);   // neg side stores plain j
    if (!valid) { pj = 0; nj = 0; }
    float4 a = g_zn[i * 32 + lane];
    float4 p = g_zn[pj * 32 + lane];
    float4 n = g_zn[nj * 32 + lane];
    const float e = 1e-6f;
    float dx, s1 = 0.f, s2 = 0.f;
    dx = a.x - p.x + e; s1 += dx * dx;
    dx = a.y - p.y + e; s1 += dx * dx;
    dx = a.z - p.z + e; s1 += dx * dx;
    dx = a.w - p.w + e; s1 += dx * dx;
    dx = a.x - n.x + e; s2 += dx * dx;
    dx = a.y - n.y + e; s2 += dx * dx;
    dx = a.z - n.z + e; s2 += dx * dx;
    dx = a.w - n.w + e; s2 += dx * dx;
#pragma unroll
    for (int o = 16; o; o >>= 1) {
        s1 += __shfl_xor_sync(0xFFFFFFFFu, s1, o);
        s2 += __shfl_xor_sync(0xFFFFFFFFu, s2, o);
    }
    if (lane == 0) {
        float per = fmaxf(sqrtf(s1) - sqrtf(s2) + 0.2f, 0.f);
        sper[w] = valid ? per : 0.f;
        scnt[w] = valid ? 1 : 0;
    }
    __syncthreads();
    if (threadIdx.x == 0) {
        float bs = 0.f;
        int bc = 0;
#pragma unroll
        for (int k = 0; k < 8; k++) { bs += sper[k]; bc += scnt[k]; }
        unsigned long long fx = (unsigned long long)(bs * 16777216.0f + 0.5f);
        atomicAdd(&g_acc, (fx << 14) | (unsigned long long)bc);
        __threadfence();
        unsigned old = atomicAdd(&g_done, 1u);
        if (old == gridDim.x - 1) {
            unsigned long long acc = atomicAdd(&g_acc, 0ull);
            unsigned cnt = (unsigned)(acc & 0x3FFFull);
            float sum = (float)(acc >> 14) * (1.0f / 16777216.0f);
            out[0] = cnt ? sum / (float)cnt : 0.f;
        }
    }
}

extern "C" void kernel_launch(void* const* d_in, const int* in_sizes, int n_in,
                              void* d_out, int out_size) {
    const float* z = (const float*)d_in[0];
    const int* lab = (const int*)d_in[1];
    const int* sub = (const int*)d_in[2];
    cudaFuncSetAttribute(k_mine, cudaFuncAttributeMaxDynamicSharedMemorySize, SM_TOT);
    k_init<<<1, 256>>>();
    k_hist<<<32, 256>>>(lab, sub);
    k_prep<<<1024, 256>>>(z, lab, sub);
    k_scatter<<<32, 256>>>();
    k_mine<<<3072, 256, SM_TOT>>>();
    k_pair<<<1024, 256>>>((float*)d_out);
}